// round 2
// baseline (speedup 1.0000x reference)
#include <cuda_runtime.h>
#include <math.h>

#define B_ 16
#define C_ 64
#define T_ 2048
#define H_ 4
#define HD_ 16
#define NR_ 1024
#define TOPK_ 40
#define C2_ 128

// ---------------- scratch (device globals; no allocation) ----------------
__device__ float g_xn[B_*C_*T_];
__device__ float g_q [B_*C_*T_];
__device__ float g_k [B_*C_*T_];
__device__ float g_v [B_*C_*T_];
__device__ float g_qr[B_*C_*NR_];
__device__ float g_kr[B_*C_*NR_];
__device__ float g_ar[B_*NR_*NR_];
__device__ int   g_idx[B_*NR_*TOPK_];
__device__ float g_kbt[B_*H_*NR_*32];
__device__ float g_vbt[B_*H_*NR_*32];
__device__ float g_o [B_*C_*T_];
__device__ float g_x2[B_*C_*T_];
__device__ float g_h1[B_*C2_*T_];
__device__ float g_h2[B_*C2_*T_];
__device__ float2 g_tw[1024];

__device__ __forceinline__ float bnsc(float g) { return g * rsqrtf(1.0f + 1e-5f); }

// ---------------- K0: twiddle table ----------------
__global__ void twiddle_kernel() {
    int k = blockIdx.x * blockDim.x + threadIdx.x;
    if (k < 1024) {
        double a = -2.0 * 3.14159265358979323846 * (double)k / 2048.0;
        g_tw[k] = make_float2((float)cos(a), (float)sin(a));
    }
}

// ---------------- K1: xn = bn(x) ----------------
__global__ void bn_in_kernel(const float* __restrict__ x,
                             const float* __restrict__ g,
                             const float* __restrict__ b) {
    int i = blockIdx.x * 256 + threadIdx.x;
    int c = (i / T_) & (C_ - 1);
    g_xn[i] = x[i] * bnsc(g[c]) + b[c];
}

// ---------------- K2: conv k=3 pad=1 + BN (q / k) ----------------
__global__ void __launch_bounds__(256) conv3_kernel(const float* __restrict__ w,
                                                    const float* __restrict__ bg,
                                                    const float* __restrict__ bb,
                                                    int which) {
    // grid: B*32*2 = 1024
    int blk = blockIdx.x;
    int oh = blk & 1;
    int tile = blk >> 1;
    int b = tile >> 5;
    int tt0 = (tile & 31) << 6;
    __shared__ float s_in[64][68];
    __shared__ float s_w[3 * 64 * 32];   // [(h*64+ci)*32 + ocl]
    const float* inb = g_xn + b * C_ * T_;
    for (int i = threadIdx.x; i < 64 * 66; i += 256) {
        int ci = i / 66, j = i % 66;
        int gt = tt0 + j - 1;
        s_in[ci][j] = (gt >= 0 && gt < T_) ? inb[ci * T_ + gt] : 0.f;
    }
    for (int i = threadIdx.x; i < 3 * 64 * 32; i += 256) {
        int ocl = i & 31;
        int rest = i >> 5;
        int ci = rest & 63;
        int h = rest >> 6;
        int oc = oh * 32 + ocl;
        s_w[i] = w[(oc * 64 + ci) * 3 + h];
    }
    __syncthreads();
    int tl = threadIdx.x & 63;
    int og = threadIdx.x >> 6;            // 4 groups x 8 oc
    float acc[8] = {0,0,0,0,0,0,0,0};
    for (int ci = 0; ci < 64; ci++) {
#pragma unroll
        for (int h = 0; h < 3; h++) {
            float xv = s_in[ci][tl + h];
            const float4* wp = (const float4*)&s_w[(h * 64 + ci) * 32 + og * 8];
            float4 w0 = wp[0], w1 = wp[1];
            acc[0] += xv * w0.x; acc[1] += xv * w0.y;
            acc[2] += xv * w0.z; acc[3] += xv * w0.w;
            acc[4] += xv * w1.x; acc[5] += xv * w1.y;
            acc[6] += xv * w1.z; acc[7] += xv * w1.w;
        }
    }
    int t = tt0 + tl;
    float* outp = which ? g_k : g_q;
#pragma unroll
    for (int j = 0; j < 8; j++) {
        int oc = oh * 32 + og * 8 + j;
        outp[(b * C_ + oc) * T_ + t] = acc[j] * bnsc(bg[oc]) + bb[oc];
    }
}

// ---------------- K3: conv k=1 (v) ----------------
__global__ void __launch_bounds__(256) conv1v_kernel(const float* __restrict__ w) {
    int blk = blockIdx.x;                 // 512
    int b = blk >> 5;
    int tt0 = (blk & 31) << 6;
    __shared__ float s_in[64][64];
    __shared__ float s_w[64 * 64];        // [ci*64+oc]
    const float* inb = g_xn + b * C_ * T_;
    for (int i = threadIdx.x; i < 4096; i += 256) {
        int ci = i >> 6, j = i & 63;
        s_in[ci][j] = inb[ci * T_ + tt0 + j];
    }
    for (int i = threadIdx.x; i < 4096; i += 256) {
        int ci = i >> 6, oc = i & 63;
        s_w[ci * 64 + oc] = w[oc * 64 + ci];
    }
    __syncthreads();
    int tl = threadIdx.x & 63;
    int og = threadIdx.x >> 6;            // 4 groups x 16 oc
    float acc[16];
#pragma unroll
    for (int j = 0; j < 16; j++) acc[j] = 0.f;
    for (int ci = 0; ci < 64; ci++) {
        float xv = s_in[ci][tl];
        const float4* wp = (const float4*)&s_w[ci * 64 + og * 16];
#pragma unroll
        for (int q = 0; q < 4; q++) {
            float4 wv = wp[q];
            acc[q * 4 + 0] += xv * wv.x; acc[q * 4 + 1] += xv * wv.y;
            acc[q * 4 + 2] += xv * wv.z; acc[q * 4 + 3] += xv * wv.w;
        }
    }
    int t = tt0 + tl;
#pragma unroll
    for (int j = 0; j < 16; j++) {
        int oc = og * 16 + j;
        g_v[(b * C_ + oc) * T_ + t] = acc[j];
    }
}

// ---------------- K4: q_r, k_r (mean over RS=2) ----------------
__global__ void reduce_rs_kernel() {
    int i = blockIdx.x * 256 + threadIdx.x;   // over B*C*NR
    int r = i & (NR_ - 1);
    int bc = i >> 10;
    int base = bc * T_ + r * 2;
    g_qr[i] = 0.5f * (g_q[base] + g_q[base + 1]);
    g_kr[i] = 0.5f * (g_k[base] + g_k[base + 1]);
}

// ---------------- K5: a_r = q_r^T k_r  (per-b 1024x1024x64 GEMM) ----------------
__global__ void __launch_bounds__(256) gemm_ar_kernel() {
    // grid: B * 8 * 16 = 2048 ; tiles 128(m) x 64(n), K=64
    int blk = blockIdx.x;
    int b = blk >> 7;
    int mt = (blk >> 4) & 7;
    int nt = blk & 15;
    int m0 = mt * 128, n0 = nt * 64;
    __shared__ float As[64][128];
    __shared__ float Bs[64][64];
    const float* qp = g_qr + b * C_ * NR_;
    const float* kp = g_kr + b * C_ * NR_;
    for (int i = threadIdx.x; i < 64 * 128; i += 256) {
        int c = i >> 7, m = i & 127;
        As[c][m] = qp[c * NR_ + m0 + m];
    }
    for (int i = threadIdx.x; i < 64 * 64; i += 256) {
        int c = i >> 6, n = i & 63;
        Bs[c][n] = kp[c * NR_ + n0 + n];
    }
    __syncthreads();
    int tm = threadIdx.x >> 4;     // 16 -> rows tm*8..tm*8+7
    int tn = threadIdx.x & 15;     // cols tn*4..tn*4+3
    float acc[8][4];
#pragma unroll
    for (int i = 0; i < 8; i++)
#pragma unroll
        for (int j = 0; j < 4; j++) acc[i][j] = 0.f;
    for (int c = 0; c < 64; c++) {
        float4 a0 = *(const float4*)&As[c][tm * 8];
        float4 a1 = *(const float4*)&As[c][tm * 8 + 4];
        float4 bv = *(const float4*)&Bs[c][tn * 4];
        float ar[8] = {a0.x, a0.y, a0.z, a0.w, a1.x, a1.y, a1.z, a1.w};
        float br[4] = {bv.x, bv.y, bv.z, bv.w};
#pragma unroll
        for (int i = 0; i < 8; i++)
#pragma unroll
            for (int j = 0; j < 4; j++) acc[i][j] += ar[i] * br[j];
    }
#pragma unroll
    for (int i = 0; i < 8; i++) {
        int m = m0 + tm * 8 + i;
        float4 o4 = make_float4(acc[i][0], acc[i][1], acc[i][2], acc[i][3]);
        *(float4*)&g_ar[(size_t)(b * NR_ + m) * NR_ + n0 + tn * 4] = o4;
    }
}

// ---------------- K6: top-40 per row ----------------
__global__ void __launch_bounds__(256) topk_kernel() {
    int row = blockIdx.x;                 // B*NR
    const float* ap = g_ar + (size_t)row * NR_;
    __shared__ unsigned long long sv[1024];
    __shared__ unsigned long long swin[8];
    for (int i = threadIdx.x; i < 1024; i += 256) {
        unsigned u = __float_as_uint(ap[i]);
        u = (u & 0x80000000u) ? ~u : (u | 0x80000000u);
        sv[i] = ((unsigned long long)u << 32) | (unsigned)i;
    }
    __syncthreads();
    int lane = threadIdx.x & 31, wid = threadIdx.x >> 5;
    int* outp = g_idx + row * TOPK_;
    for (int it = 0; it < TOPK_; it++) {
        unsigned long long m = 0ull;
#pragma unroll
        for (int j = 0; j < 4; j++) {
            unsigned long long v = sv[threadIdx.x + j * 256];
            m = v > m ? v : m;
        }
#pragma unroll
        for (int o = 16; o; o >>= 1) {
            unsigned long long v = __shfl_xor_sync(0xffffffffu, m, o);
            m = v > m ? v : m;
        }
        if (lane == 0) swin[wid] = m;
        __syncthreads();
        if (threadIdx.x == 0) {
            unsigned long long mm = swin[0];
#pragma unroll
            for (int j = 1; j < 8; j++) { unsigned long long v = swin[j]; mm = v > mm ? v : mm; }
            swin[0] = mm;
        }
        __syncthreads();
        unsigned long long win = swin[0];
        int idx = (int)(win & 0xffffffffu);
        if ((idx & 255) == threadIdx.x) sv[idx] = 0ull;
        if (threadIdx.x == 0) outp[it] = idx;
        __syncthreads();
    }
}

// ---------------- K7: transpose k,v -> [B,H,NR,32] blocks ----------------
__global__ void transpose_kv_kernel() {
    int o = blockIdx.x * 256 + threadIdx.x;   // B*H*NR*32 = 2M
    int d = o & 15;
    int s = (o >> 4) & 1;
    int r = (o >> 5) & (NR_ - 1);
    int bh = o >> 15;
    int b = bh >> 2, h = bh & 3;
    int src = (b * C_ + h * HD_ + d) * T_ + r * 2 + s;
    g_kbt[o] = g_k[src];
    g_vbt[o] = g_v[src];
}

// ---------------- K8: gathered attention, warp per (b,h,r) ----------------
__global__ void __launch_bounds__(128) attn_kernel() {
    int gw = blockIdx.x * 4 + (threadIdx.x >> 5);   // B*H*NR = 65536
    int lane = threadIdx.x & 31;
    int w = threadIdx.x >> 5;
    int r = gw & (NR_ - 1);
    int bh = gw >> 10;
    int b = bh >> 2, h = bh & 3;
    __shared__ float s_q[4][32];
    __shared__ float s_l[4][160];
    __shared__ float s_vv[4][1280];
    {
        int d = lane & 15, s = lane >> 4;
        s_q[w][lane] = g_q[(b * C_ + h * HD_ + d) * T_ + r * 2 + s];
    }
    __syncwarp();
    const int* idxp = g_idx + (b * NR_ + r) * TOPK_;
    for (int kk = lane; kk < 80; kk += 32) {
        int j = kk >> 1, sp = kk & 1;
        int bi = idxp[j];
        const float4* kp = (const float4*)&g_kbt[((size_t)(bh * NR_ + bi)) * 32 + sp * 16];
        const float4* vp = (const float4*)&g_vbt[((size_t)(bh * NR_ + bi)) * 32 + sp * 16];
        float kv[16];
        float4 k0 = kp[0], k1 = kp[1], k2 = kp[2], k3 = kp[3];
        kv[0]=k0.x; kv[1]=k0.y; kv[2]=k0.z; kv[3]=k0.w;
        kv[4]=k1.x; kv[5]=k1.y; kv[6]=k1.z; kv[7]=k1.w;
        kv[8]=k2.x; kv[9]=k2.y; kv[10]=k2.z; kv[11]=k2.w;
        kv[12]=k3.x; kv[13]=k3.y; kv[14]=k3.z; kv[15]=k3.w;
        float l0 = 0.f, l1 = 0.f;
#pragma unroll
        for (int dd = 0; dd < 16; dd++) {
            l0 += kv[dd] * s_q[w][dd];
            l1 += kv[dd] * s_q[w][16 + dd];
        }
        s_l[w][kk]      = l0 * 0.125f;
        s_l[w][80 + kk] = l1 * 0.125f;
        float4* dst = (float4*)&s_vv[w][kk * 16];
        dst[0] = vp[0]; dst[1] = vp[1]; dst[2] = vp[2]; dst[3] = vp[3];
    }
    __syncwarp();
#pragma unroll
    for (int s = 0; s < 2; s++) {
        float vals[3];
        float m = -1e30f;
        int cnt = 0;
        for (int kk = lane; kk < 80; kk += 32) { vals[cnt] = s_l[w][s * 80 + kk]; m = fmaxf(m, vals[cnt]); cnt++; }
#pragma unroll
        for (int o = 16; o; o >>= 1) m = fmaxf(m, __shfl_xor_sync(0xffffffffu, m, o));
        float sum = 0.f;
        cnt = 0;
        for (int kk = lane; kk < 80; kk += 32) { float e = expf(vals[cnt] - m); vals[cnt] = e; sum += e; cnt++; }
#pragma unroll
        for (int o = 16; o; o >>= 1) sum += __shfl_xor_sync(0xffffffffu, sum, o);
        float inv = 1.f / sum;
        cnt = 0;
        for (int kk = lane; kk < 80; kk += 32) { s_l[w][s * 80 + kk] = vals[cnt] * inv; cnt++; }
    }
    __syncwarp();
    {
        int s = lane >> 4, d = lane & 15;
        float acc = 0.f;
#pragma unroll 16
        for (int kk = 0; kk < 80; kk++) acc += s_l[w][s * 80 + kk] * s_vv[w][kk * 16 + d];
        g_o[(b * C_ + h * HD_ + d) * T_ + r * 2 + s] = acc;
    }
}

// ---------------- K9: o + lepe, out-conv, residual -> x2 ----------------
__global__ void __launch_bounds__(256) fuse_o_kernel(const float* __restrict__ x,
                                                     const float* __restrict__ lw,
                                                     const float* __restrict__ lb,
                                                     const float* __restrict__ ow,
                                                     const float* __restrict__ ob) {
    int blk = blockIdx.x;                 // 512
    int b = blk >> 5;
    int tt0 = (blk & 31) << 6;
    __shared__ float s_tmp[64][68];
    __shared__ float s_w[64 * 64];
    for (int i = threadIdx.x; i < 4096; i += 256) {
        int c = i >> 6, tl = i & 63;
        int t = tt0 + tl;
        const float* vp = g_v + (b * C_ + c) * T_;
        float vm1 = (t > 0) ? vp[t - 1] : 0.f;
        float v0 = vp[t];
        float vp1 = (t < T_ - 1) ? vp[t + 1] : 0.f;
        float lep = lw[c * 3 + 0] * vm1 + lw[c * 3 + 1] * v0 + lw[c * 3 + 2] * vp1 + lb[c];
        s_tmp[c][tl] = g_o[(b * C_ + c) * T_ + t] + lep;
    }
    for (int i = threadIdx.x; i < 4096; i += 256) {
        int ci = i >> 6, oc = i & 63;
        s_w[ci * 64 + oc] = ow[oc * 64 + ci];
    }
    __syncthreads();
    int tl = threadIdx.x & 63;
    int og = threadIdx.x >> 6;
    float acc[16];
#pragma unroll
    for (int j = 0; j < 16; j++) acc[j] = 0.f;
    for (int ci = 0; ci < 64; ci++) {
        float xv = s_tmp[ci][tl];
        const float4* wp = (const float4*)&s_w[ci * 64 + og * 16];
#pragma unroll
        for (int q = 0; q < 4; q++) {
            float4 wv = wp[q];
            acc[q * 4 + 0] += xv * wv.x; acc[q * 4 + 1] += xv * wv.y;
            acc[q * 4 + 2] += xv * wv.z; acc[q * 4 + 3] += xv * wv.w;
        }
    }
    int t = tt0 + tl;
#pragma unroll
    for (int j = 0; j < 16; j++) {
        int oc = og * 16 + j;
        size_t o = (size_t)(b * C_ + oc) * T_ + t;
        g_x2[o] = acc[j] + ob[oc] + x[o];
    }
}

// ---------------- K10: h1 = relu(bn1(fc1 @ bn(x2))) ----------------
__global__ void __launch_bounds__(256) fc1_kernel(const float* __restrict__ n2g,
                                                  const float* __restrict__ n2b,
                                                  const float* __restrict__ w,
                                                  const float* __restrict__ bg,
                                                  const float* __restrict__ bb) {
    int blk = blockIdx.x;                 // 512
    int b = blk >> 5;
    int tt0 = (blk & 31) << 6;
    __shared__ float s_in[64][64];
    __shared__ float s_w[64 * 128];
    for (int i = threadIdx.x; i < 4096; i += 256) {
        int ci = i >> 6, tl = i & 63;
        s_in[ci][tl] = g_x2[(size_t)(b * C_ + ci) * T_ + tt0 + tl] * bnsc(n2g[ci]) + n2b[ci];
    }
    for (int i = threadIdx.x; i < 8192; i += 256) {
        int oc = i & 127, ci = i >> 7;
        s_w[ci * 128 + oc] = w[oc * 64 + ci];
    }
    __syncthreads();
    int tl = threadIdx.x & 63;
    int og = threadIdx.x >> 6;            // 4 groups x 32 oc
    float acc[32];
#pragma unroll
    for (int j = 0; j < 32; j++) acc[j] = 0.f;
    for (int ci = 0; ci < 64; ci++) {
        float xv = s_in[ci][tl];
        const float4* wp = (const float4*)&s_w[ci * 128 + og * 32];
#pragma unroll
        for (int q = 0; q < 8; q++) {
            float4 wv = wp[q];
            acc[q * 4 + 0] += xv * wv.x; acc[q * 4 + 1] += xv * wv.y;
            acc[q * 4 + 2] += xv * wv.z; acc[q * 4 + 3] += xv * wv.w;
        }
    }
    int t = tt0 + tl;
#pragma unroll
    for (int j = 0; j < 32; j++) {
        int oc = og * 32 + j;
        float r = acc[j] * bnsc(bg[oc]) + bb[oc];
        g_h1[(size_t)(b * C2_ + oc) * T_ + t] = fmaxf(r, 0.f);
    }
}

// ---------------- K11: FFT -> diag complex mix + relu -> IFFT (real) ----------------
__device__ __forceinline__ float2 cmulf(float2 a, float2 b) {
    return make_float2(a.x * b.x - a.y * b.y, a.x * b.y + a.y * b.x);
}

__global__ void __launch_bounds__(256) fft_kernel(const float* __restrict__ fr,
                                                  const float* __restrict__ fi,
                                                  const float* __restrict__ frb,
                                                  const float* __restrict__ fib) {
    int bc = blockIdx.x;                  // 2048
    int b = bc >> 7, cc = bc & 127;
    __shared__ float2 sa[2048];
    __shared__ float2 sb[2048];
    const float* inp = g_h1 + (size_t)(b * C2_ + cc) * T_;
    for (int t = threadIdx.x; t < 2048; t += 256) {
        int p = __brev((unsigned)t) >> 21;
        sa[p] = make_float2(inp[t], 0.f);
    }
    __syncthreads();
    // forward DIT
    int s = 0;
    for (int L = 1; L < 2048; L <<= 1, s++) {
        for (int j = threadIdx.x; j < 1024; j += 256) {
            int pos = j & (L - 1);
            int k0 = ((j >> s) << (s + 1)) + pos;
            float2 wv = g_tw[pos << (10 - s)];
            float2 u = sa[k0];
            float2 t2 = cmulf(wv, sa[k0 + L]);
            sa[k0]     = make_float2(u.x + t2.x, u.y + t2.y);
            sa[k0 + L] = make_float2(u.x - t2.x, u.y - t2.y);
        }
        __syncthreads();
    }
    // pointwise diag mix + relu, write bit-reversed into sb
    float frd = fr[cc * 128 + cc];
    float fid = fi[cc * 128 + cc];
    float rb = frb[cc], ib = fib[cc];
    const float sc = 0.022097086912079612f;   // 1/sqrt(2048)
    for (int n = threadIdx.x; n < 2048; n += 256) {
        float re = sa[n].x * sc, im = sa[n].y * sc;
        float xr = fmaxf(re * frd - im * fid + rb, 0.f);
        float xi = fmaxf(im * frd + re * fid + ib, 0.f);
        sb[__brev((unsigned)n) >> 21] = make_float2(xr, xi);
    }
    __syncthreads();
    // inverse DIT (conjugate twiddles)
    s = 0;
    for (int L = 1; L < 2048; L <<= 1, s++) {
        for (int j = threadIdx.x; j < 1024; j += 256) {
            int pos = j & (L - 1);
            int k0 = ((j >> s) << (s + 1)) + pos;
            float2 wv = g_tw[pos << (10 - s)];
            wv.y = -wv.y;
            float2 u = sb[k0];
            float2 t2 = cmulf(wv, sb[k0 + L]);
            sb[k0]     = make_float2(u.x + t2.x, u.y + t2.y);
            sb[k0 + L] = make_float2(u.x - t2.x, u.y - t2.y);
        }
        __syncthreads();
    }
    float* outp = g_h2 + (size_t)(b * C2_ + cc) * T_;
    for (int t = threadIdx.x; t < 2048; t += 256) {
        outp[t] = sb[t].x * sc;
    }
}

// ---------------- K12: out = x2 + bn2(fc2 @ h2) ----------------
__global__ void __launch_bounds__(256) fc2_kernel(const float* __restrict__ w,
                                                  const float* __restrict__ bg,
                                                  const float* __restrict__ bb,
                                                  float* __restrict__ out) {
    int blk = blockIdx.x;                 // B*64 = 1024, t-tile 32
    int b = blk >> 6;
    int tt0 = (blk & 63) << 5;
    __shared__ float s_in[128][32];
    __shared__ float s_w[128 * 64];
    for (int i = threadIdx.x; i < 4096; i += 256) {
        int ci = i >> 5, tl = i & 31;
        s_in[ci][tl] = g_h2[(size_t)(b * C2_ + ci) * T_ + tt0 + tl];
    }
    for (int i = threadIdx.x; i < 8192; i += 256) {
        int oc = i & 63, ci = i >> 6;
        s_w[ci * 64 + oc] = w[oc * 128 + ci];
    }
    __syncthreads();
    int tl = threadIdx.x & 31;
    int og = threadIdx.x >> 5;            // 8 groups x 8 oc
    float acc[8];
#pragma unroll
    for (int j = 0; j < 8; j++) acc[j] = 0.f;
    for (int ci = 0; ci < 128; ci++) {
        float xv = s_in[ci][tl];
        const float4* wp = (const float4*)&s_w[ci * 64 + og * 8];
        float4 w0 = wp[0], w1 = wp[1];
        acc[0] += xv * w0.x; acc[1] += xv * w0.y;
        acc[2] += xv * w0.z; acc[3] += xv * w0.w;
        acc[4] += xv * w1.x; acc[5] += xv * w1.y;
        acc[6] += xv * w1.z; acc[7] += xv * w1.w;
    }
    int t = tt0 + tl;
#pragma unroll
    for (int j = 0; j < 8; j++) {
        int oc = og * 8 + j;
        size_t o = (size_t)(b * C_ + oc) * T_ + t;
        out[o] = acc[j] * bnsc(bg[oc]) + bb[oc] + g_x2[o];
    }
}

// ---------------- launch ----------------
extern "C" void kernel_launch(void* const* d_in, const int* in_sizes, int n_in,
                              void* d_out, int out_size) {
    const float* x      = (const float*)d_in[0];
    const float* n1_g   = (const float*)d_in[1];
    const float* n1_b   = (const float*)d_in[2];
    const float* wq     = (const float*)d_in[3];
    const float* bnq_g  = (const float*)d_in[4];
    const float* bnq_b  = (const float*)d_in[5];
    const float* wk     = (const float*)d_in[6];
    const float* bnk_g  = (const float*)d_in[7];
    const float* bnk_b  = (const float*)d_in[8];
    const float* wv     = (const float*)d_in[9];
    const float* lepe_w = (const float*)d_in[10];
    const float* lepe_b = (const float*)d_in[11];
    const float* out_w  = (const float*)d_in[12];
    const float* out_b  = (const float*)d_in[13];
    const float* n2_g   = (const float*)d_in[14];
    const float* n2_b   = (const float*)d_in[15];
    const float* fc1_w  = (const float*)d_in[16];
    const float* bn1_g  = (const float*)d_in[17];
    const float* bn1_b  = (const float*)d_in[18];
    const float* fr     = (const float*)d_in[19];
    const float* fi     = (const float*)d_in[20];
    const float* frb    = (const float*)d_in[21];
    const float* fib    = (const float*)d_in[22];
    const float* fc2_w  = (const float*)d_in[23];
    const float* bn2_g  = (const float*)d_in[24];
    const float* bn2_b  = (const float*)d_in[25];
    float* out = (float*)d_out;

    twiddle_kernel<<<4, 256>>>();
    bn_in_kernel<<<(B_*C_*T_)/256, 256>>>(x, n1_g, n1_b);
    conv3_kernel<<<1024, 256>>>(wq, bnq_g, bnq_b, 0);
    conv3_kernel<<<1024, 256>>>(wk, bnk_g, bnk_b, 1);
    conv1v_kernel<<<512, 256>>>(wv);
    reduce_rs_kernel<<<(B_*C_*NR_)/256, 256>>>();
    gemm_ar_kernel<<<2048, 256>>>();
    topk_kernel<<<B_*NR_, 256>>>();
    transpose_kv_kernel<<<(B_*H_*NR_*32)/256, 256>>>();
    attn_kernel<<<(B_*H_*NR_)/4, 128>>>();
    fuse_o_kernel<<<512, 256>>>(x, lepe_w, lepe_b, out_w, out_b);
    fc1_kernel<<<512, 256>>>(n2_g, n2_b, fc1_w, bn1_g, bn1_b);
    fft_kernel<<<B_*C2_, 256>>>(fr, fi, frb, fib);
    fc2_kernel<<<1024, 256>>>(fc2_w, bn2_g, bn2_b, out);
    (void)in_sizes; (void)n_in; (void)out_size;
}

// round 3
// speedup vs baseline: 1.8837x; 1.8837x over previous
#include <cuda_runtime.h>
#include <math.h>

#define B_ 16
#define C_ 64
#define T_ 2048
#define H_ 4
#define HD_ 16
#define NR_ 1024
#define TOPK_ 40
#define C2_ 128

// ---------------- scratch (device globals; no allocation) ----------------
__device__ float g_xn[B_*C_*T_];
__device__ float g_q [B_*C_*T_];
__device__ float g_k [B_*C_*T_];
__device__ float g_v [B_*C_*T_];
__device__ float g_qr[B_*C_*NR_];
__device__ float g_kr[B_*C_*NR_];
__device__ float g_ar[B_*NR_*NR_];
__device__ int   g_idx[B_*NR_*TOPK_];
__device__ float g_kbt[B_*H_*NR_*32];
__device__ float g_vbt[B_*H_*NR_*32];
__device__ float g_o [B_*C_*T_];
__device__ float g_x2[B_*C_*T_];
__device__ float g_h1[B_*C2_*T_];
__device__ float g_h2[B_*C2_*T_];
__device__ float2 g_tw[1024];

__device__ __forceinline__ float bnsc(float g) { return g * rsqrtf(1.0f + 1e-5f); }

// ---------------- K0: twiddle table ----------------
__global__ void twiddle_kernel() {
    int k = blockIdx.x * blockDim.x + threadIdx.x;
    if (k < 1024) {
        double a = -2.0 * 3.14159265358979323846 * (double)k / 2048.0;
        g_tw[k] = make_float2((float)cos(a), (float)sin(a));
    }
}

// ---------------- K1: xn = bn(x) ----------------
__global__ void bn_in_kernel(const float* __restrict__ x,
                             const float* __restrict__ g,
                             const float* __restrict__ b) {
    int i = blockIdx.x * 256 + threadIdx.x;
    int c = (i / T_) & (C_ - 1);
    g_xn[i] = x[i] * bnsc(g[c]) + b[c];
}

// ---------------- K2: conv k=3 pad=1 + BN, q and k fused grid ----------------
__global__ void __launch_bounds__(128) conv3qk_kernel(const float* __restrict__ wq,
                                                      const float* __restrict__ bgq,
                                                      const float* __restrict__ bbq,
                                                      const float* __restrict__ wk,
                                                      const float* __restrict__ bgk,
                                                      const float* __restrict__ bbk) {
    // grid 1024: [0]=oh, [4:1]=ttile(16), [8:5]=b(16), [9]=which
    int blk = blockIdx.x;
    int oh = blk & 1;
    int tt = (blk >> 1) & 15;
    int b  = (blk >> 5) & 15;
    int which = blk >> 9;
    int tt0 = tt * 128;

    const float* w  = which ? wk  : wq;
    const float* bg = which ? bgk : bgq;
    const float* bb = which ? bbk : bbq;
    float* outp     = which ? g_k : g_q;

    __shared__ float s_in[32][132];
    __shared__ float s_w[3 * 32 * 32];   // [(h*32+ci)*32 + ocl]

    const float* inb = g_xn + b * C_ * T_;
    int tid = threadIdx.x;
    int tl4 = (tid & 31) * 4;
    int og  = tid >> 5;                  // 4 groups x 8 oc

    float acc[4][8];
#pragma unroll
    for (int t = 0; t < 4; t++)
#pragma unroll
        for (int j = 0; j < 8; j++) acc[t][j] = 0.f;

    for (int chunk = 0; chunk < 2; chunk++) {
        int ci0 = chunk * 32;
        for (int i = tid; i < 32 * 132; i += 128) {
            int ci = i / 132, jj = i % 132;
            int gt = tt0 + jj - 1;
            s_in[ci][jj] = (gt >= 0 && gt < T_) ? inb[(ci0 + ci) * T_ + gt] : 0.f;
        }
        for (int i = tid; i < 3072; i += 128) {
            int ocl = i & 31;
            int r = i >> 5;
            int ci = r & 31;
            int h = r >> 5;
            s_w[i] = w[((oh * 32 + ocl) * 64 + ci0 + ci) * 3 + h];
        }
        __syncthreads();
        for (int ci = 0; ci < 32; ci++) {
            float xs[6];
            float4 xa = *(const float4*)&s_in[ci][tl4];
            xs[0] = xa.x; xs[1] = xa.y; xs[2] = xa.z; xs[3] = xa.w;
            xs[4] = s_in[ci][tl4 + 4];
            xs[5] = s_in[ci][tl4 + 5];
#pragma unroll
            for (int h = 0; h < 3; h++) {
                const float4* wp = (const float4*)&s_w[(h * 32 + ci) * 32 + og * 8];
                float4 w0 = wp[0], w1 = wp[1];
#pragma unroll
                for (int t = 0; t < 4; t++) {
                    float xv = xs[t + h];
                    acc[t][0] += xv * w0.x; acc[t][1] += xv * w0.y;
                    acc[t][2] += xv * w0.z; acc[t][3] += xv * w0.w;
                    acc[t][4] += xv * w1.x; acc[t][5] += xv * w1.y;
                    acc[t][6] += xv * w1.z; acc[t][7] += xv * w1.w;
                }
            }
        }
        __syncthreads();
    }
#pragma unroll
    for (int j = 0; j < 8; j++) {
        int oc = oh * 32 + og * 8 + j;
        float s = bnsc(bg[oc]), bi = bb[oc];
        float4 o4 = make_float4(acc[0][j] * s + bi, acc[1][j] * s + bi,
                                acc[2][j] * s + bi, acc[3][j] * s + bi);
        *(float4*)&outp[(b * C_ + oc) * T_ + tt0 + tl4] = o4;
    }
}

// ---------------- K3: conv k=1 (v) ----------------
__global__ void __launch_bounds__(256) conv1v_kernel(const float* __restrict__ w) {
    int blk = blockIdx.x;                 // 512
    int b = blk >> 5;
    int tt0 = (blk & 31) << 6;
    __shared__ float s_in[64][64];
    __shared__ float s_w[64 * 64];        // [ci*64+oc]
    const float* inb = g_xn + b * C_ * T_;
    for (int i = threadIdx.x; i < 4096; i += 256) {
        int ci = i >> 6, j = i & 63;
        s_in[ci][j] = inb[ci * T_ + tt0 + j];
    }
    for (int i = threadIdx.x; i < 4096; i += 256) {
        int ci = i >> 6, oc = i & 63;
        s_w[ci * 64 + oc] = w[oc * 64 + ci];
    }
    __syncthreads();
    int tl = threadIdx.x & 63;
    int og = threadIdx.x >> 6;            // 4 groups x 16 oc
    float acc[16];
#pragma unroll
    for (int j = 0; j < 16; j++) acc[j] = 0.f;
    for (int ci = 0; ci < 64; ci++) {
        float xv = s_in[ci][tl];
        const float4* wp = (const float4*)&s_w[ci * 64 + og * 16];
#pragma unroll
        for (int q = 0; q < 4; q++) {
            float4 wv = wp[q];
            acc[q * 4 + 0] += xv * wv.x; acc[q * 4 + 1] += xv * wv.y;
            acc[q * 4 + 2] += xv * wv.z; acc[q * 4 + 3] += xv * wv.w;
        }
    }
    int t = tt0 + tl;
#pragma unroll
    for (int j = 0; j < 16; j++) {
        int oc = og * 16 + j;
        g_v[(b * C_ + oc) * T_ + t] = acc[j];
    }
}

// ---------------- K4: q_r, k_r (mean over RS=2) ----------------
__global__ void reduce_rs_kernel() {
    int i = blockIdx.x * 256 + threadIdx.x;   // over B*C*NR
    int r = i & (NR_ - 1);
    int bc = i >> 10;
    int base = bc * T_ + r * 2;
    g_qr[i] = 0.5f * (g_q[base] + g_q[base + 1]);
    g_kr[i] = 0.5f * (g_k[base] + g_k[base + 1]);
}

// ---------------- K5: a_r = q_r^T k_r  (per-b 1024x1024x64 GEMM) ----------------
__global__ void __launch_bounds__(256) gemm_ar_kernel() {
    int blk = blockIdx.x;
    int b = blk >> 7;
    int mt = (blk >> 4) & 7;
    int nt = blk & 15;
    int m0 = mt * 128, n0 = nt * 64;
    __shared__ float As[64][128];
    __shared__ float Bs[64][64];
    const float* qp = g_qr + b * C_ * NR_;
    const float* kp = g_kr + b * C_ * NR_;
    for (int i = threadIdx.x; i < 64 * 128; i += 256) {
        int c = i >> 7, m = i & 127;
        As[c][m] = qp[c * NR_ + m0 + m];
    }
    for (int i = threadIdx.x; i < 64 * 64; i += 256) {
        int c = i >> 6, n = i & 63;
        Bs[c][n] = kp[c * NR_ + n0 + n];
    }
    __syncthreads();
    int tm = threadIdx.x >> 4;
    int tn = threadIdx.x & 15;
    float acc[8][4];
#pragma unroll
    for (int i = 0; i < 8; i++)
#pragma unroll
        for (int j = 0; j < 4; j++) acc[i][j] = 0.f;
    for (int c = 0; c < 64; c++) {
        float4 a0 = *(const float4*)&As[c][tm * 8];
        float4 a1 = *(const float4*)&As[c][tm * 8 + 4];
        float4 bv = *(const float4*)&Bs[c][tn * 4];
        float ar[8] = {a0.x, a0.y, a0.z, a0.w, a1.x, a1.y, a1.z, a1.w};
        float br[4] = {bv.x, bv.y, bv.z, bv.w};
#pragma unroll
        for (int i = 0; i < 8; i++)
#pragma unroll
            for (int j = 0; j < 4; j++) acc[i][j] += ar[i] * br[j];
    }
#pragma unroll
    for (int i = 0; i < 8; i++) {
        int m = m0 + tm * 8 + i;
        float4 o4 = make_float4(acc[i][0], acc[i][1], acc[i][2], acc[i][3]);
        *(float4*)&g_ar[(size_t)(b * NR_ + m) * NR_ + n0 + tn * 4] = o4;
    }
}

// ---------------- K6: top-40 per row via 4-level radix select ----------------
__global__ void __launch_bounds__(256) topk_kernel() {
    int row = blockIdx.x;                 // B*NR
    int tid = threadIdx.x;
    const float4* ap = (const float4*)(g_ar + (size_t)row * NR_);
    __shared__ int hist[256];
    __shared__ unsigned long long cA[1024];
    __shared__ unsigned long long cB[1024];
    __shared__ int s_thr, s_need, s_outc, s_nsrc, s_nb;

    unsigned long long kv[4];
    {
        float4 v4 = ap[tid];
        float vv[4] = {v4.x, v4.y, v4.z, v4.w};
#pragma unroll
        for (int j = 0; j < 4; j++) {
            unsigned u = __float_as_uint(vv[j]);
            u = (u & 0x80000000u) ? ~u : (u | 0x80000000u);
            kv[j] = ((unsigned long long)u << 32) | (unsigned)(tid * 4 + j);
        }
    }
    if (tid == 0) { s_outc = 0; s_need = TOPK_; }
    int* outp = g_idx + row * TOPK_;

    for (int level = 0; level < 4; level++) {
        unsigned long long* src = (level & 1) ? cA : cB;
        unsigned long long* dst = (level & 1) ? cB : cA;
        hist[tid] = 0;
        if (tid == 0) s_nb = 0;
        __syncthreads();
        int shift = 56 - level * 8;
        int nsrc = (level == 0) ? 1024 : s_nsrc;
        if (level == 0) {
#pragma unroll
            for (int j = 0; j < 4; j++)
                atomicAdd(&hist[(int)((kv[j] >> shift) & 255)], 1);
        } else {
            for (int i = tid; i < nsrc; i += 256)
                atomicAdd(&hist[(int)((src[i] >> shift) & 255)], 1);
        }
        __syncthreads();
        // warp-0 suffix scan over 256 bins (descending)
        if (tid < 32) {
            int lane = tid;
            int base = 255 - lane * 8;
            int part[8]; int tot = 0;
#pragma unroll
            for (int q = 0; q < 8; q++) { part[q] = hist[base - q]; tot += part[q]; }
            int pre = tot;
#pragma unroll
            for (int o = 1; o < 32; o <<= 1) {
                int v = __shfl_up_sync(0xffffffffu, pre, o);
                if (lane >= o) pre += v;
            }
            pre -= tot;   // count of keys in strictly higher bins
            int need = s_need;
            int cum = pre;
#pragma unroll
            for (int q = 0; q < 8; q++) {
                int c = part[q];
                if (cum < need && cum + c >= need) s_thr = base - q;
                cum += c;
            }
        }
        __syncthreads();
        int thr = s_thr;
        if (level == 0) {
#pragma unroll
            for (int j = 0; j < 4; j++) {
                int by = (int)((kv[j] >> shift) & 255);
                if (by > thr) {
                    int p = atomicAdd(&s_outc, 1);
                    outp[p] = (int)(kv[j] & 0xffffffffu);
                } else if (by == thr) {
                    int p = atomicAdd(&s_nb, 1);
                    dst[p] = kv[j];
                }
            }
        } else {
            for (int i = tid; i < nsrc; i += 256) {
                unsigned long long v = src[i];
                int by = (int)((v >> shift) & 255);
                if (by > thr) {
                    int p = atomicAdd(&s_outc, 1);
                    outp[p] = (int)(v & 0xffffffffu);
                } else if (by == thr) {
                    int p = atomicAdd(&s_nb, 1);
                    dst[p] = v;
                }
            }
        }
        __syncthreads();
        if (tid == 0) { s_need = TOPK_ - s_outc; s_nsrc = s_nb; }
        __syncthreads();
        if (s_nsrc == s_need || level == 3) {
            int base = TOPK_ - s_need;
            for (int i = tid; i < s_need; i += 256)
                outp[base + i] = (int)(dst[i] & 0xffffffffu);
            break;
        }
    }
}

// ---------------- K7: transpose k,v -> [B,H,NR,32] blocks ----------------
__global__ void transpose_kv_kernel() {
    int o = blockIdx.x * 256 + threadIdx.x;   // B*H*NR*32 = 2M
    int d = o & 15;
    int s = (o >> 4) & 1;
    int r = (o >> 5) & (NR_ - 1);
    int bh = o >> 15;
    int b = bh >> 2, h = bh & 3;
    int src = (b * C_ + h * HD_ + d) * T_ + r * 2 + s;
    g_kbt[o] = g_k[src];
    g_vbt[o] = g_v[src];
}

// ---------------- K8: gathered attention, warp per (b,h,r) ----------------
__global__ void __launch_bounds__(128) attn_kernel() {
    int gw = blockIdx.x * 4 + (threadIdx.x >> 5);   // B*H*NR = 65536
    int lane = threadIdx.x & 31;
    int w = threadIdx.x >> 5;
    int r = gw & (NR_ - 1);
    int bh = gw >> 10;
    int b = bh >> 2, h = bh & 3;
    __shared__ float s_q[4][32];
    __shared__ float s_l[4][160];
    __shared__ float s_vv[4][1280];
    {
        int d = lane & 15, s = lane >> 4;
        s_q[w][lane] = g_q[(b * C_ + h * HD_ + d) * T_ + r * 2 + s];
    }
    __syncwarp();
    const int* idxp = g_idx + (b * NR_ + r) * TOPK_;
    for (int kk = lane; kk < 80; kk += 32) {
        int j = kk >> 1, sp = kk & 1;
        int bi = idxp[j];
        const float4* kp = (const float4*)&g_kbt[((size_t)(bh * NR_ + bi)) * 32 + sp * 16];
        const float4* vp = (const float4*)&g_vbt[((size_t)(bh * NR_ + bi)) * 32 + sp * 16];
        float kvv[16];
        float4 k0 = kp[0], k1 = kp[1], k2 = kp[2], k3 = kp[3];
        kvv[0]=k0.x; kvv[1]=k0.y; kvv[2]=k0.z; kvv[3]=k0.w;
        kvv[4]=k1.x; kvv[5]=k1.y; kvv[6]=k1.z; kvv[7]=k1.w;
        kvv[8]=k2.x; kvv[9]=k2.y; kvv[10]=k2.z; kvv[11]=k2.w;
        kvv[12]=k3.x; kvv[13]=k3.y; kvv[14]=k3.z; kvv[15]=k3.w;
        float l0 = 0.f, l1 = 0.f;
#pragma unroll
        for (int dd = 0; dd < 16; dd++) {
            l0 += kvv[dd] * s_q[w][dd];
            l1 += kvv[dd] * s_q[w][16 + dd];
        }
        s_l[w][kk]      = l0 * 0.125f;
        s_l[w][80 + kk] = l1 * 0.125f;
        float4* dstp = (float4*)&s_vv[w][kk * 16];
        dstp[0] = vp[0]; dstp[1] = vp[1]; dstp[2] = vp[2]; dstp[3] = vp[3];
    }
    __syncwarp();
#pragma unroll
    for (int s = 0; s < 2; s++) {
        float vals[3];
        float m = -1e30f;
        int cnt = 0;
        for (int kk = lane; kk < 80; kk += 32) { vals[cnt] = s_l[w][s * 80 + kk]; m = fmaxf(m, vals[cnt]); cnt++; }
#pragma unroll
        for (int o = 16; o; o >>= 1) m = fmaxf(m, __shfl_xor_sync(0xffffffffu, m, o));
        float sum = 0.f;
        cnt = 0;
        for (int kk = lane; kk < 80; kk += 32) { float e = expf(vals[cnt] - m); vals[cnt] = e; sum += e; cnt++; }
#pragma unroll
        for (int o = 16; o; o >>= 1) sum += __shfl_xor_sync(0xffffffffu, sum, o);
        float inv = 1.f / sum;
        cnt = 0;
        for (int kk = lane; kk < 80; kk += 32) { s_l[w][s * 80 + kk] = vals[cnt] * inv; cnt++; }
    }
    __syncwarp();
    {
        int s = lane >> 4, d = lane & 15;
        float acc = 0.f;
#pragma unroll 16
        for (int kk = 0; kk < 80; kk++) acc += s_l[w][s * 80 + kk] * s_vv[w][kk * 16 + d];
        g_o[(b * C_ + h * HD_ + d) * T_ + r * 2 + s] = acc;
    }
}

// ---------------- K9: o + lepe, out-conv, residual -> x2 ----------------
__global__ void __launch_bounds__(256) fuse_o_kernel(const float* __restrict__ x,
                                                     const float* __restrict__ lw,
                                                     const float* __restrict__ lb,
                                                     const float* __restrict__ ow,
                                                     const float* __restrict__ ob) {
    int blk = blockIdx.x;                 // 512
    int b = blk >> 5;
    int tt0 = (blk & 31) << 6;
    __shared__ float s_tmp[64][68];
    __shared__ float s_w[64 * 64];
    for (int i = threadIdx.x; i < 4096; i += 256) {
        int c = i >> 6, tl = i & 63;
        int t = tt0 + tl;
        const float* vp = g_v + (b * C_ + c) * T_;
        float vm1 = (t > 0) ? vp[t - 1] : 0.f;
        float v0 = vp[t];
        float vp1 = (t < T_ - 1) ? vp[t + 1] : 0.f;
        float lep = lw[c * 3 + 0] * vm1 + lw[c * 3 + 1] * v0 + lw[c * 3 + 2] * vp1 + lb[c];
        s_tmp[c][tl] = g_o[(b * C_ + c) * T_ + t] + lep;
    }
    for (int i = threadIdx.x; i < 4096; i += 256) {
        int ci = i >> 6, oc = i & 63;
        s_w[ci * 64 + oc] = ow[oc * 64 + ci];
    }
    __syncthreads();
    int tl = threadIdx.x & 63;
    int og = threadIdx.x >> 6;
    float acc[16];
#pragma unroll
    for (int j = 0; j < 16; j++) acc[j] = 0.f;
    for (int ci = 0; ci < 64; ci++) {
        float xv = s_tmp[ci][tl];
        const float4* wp = (const float4*)&s_w[ci * 64 + og * 16];
#pragma unroll
        for (int q = 0; q < 4; q++) {
            float4 wv = wp[q];
            acc[q * 4 + 0] += xv * wv.x; acc[q * 4 + 1] += xv * wv.y;
            acc[q * 4 + 2] += xv * wv.z; acc[q * 4 + 3] += xv * wv.w;
        }
    }
    int t = tt0 + tl;
#pragma unroll
    for (int j = 0; j < 16; j++) {
        int oc = og * 16 + j;
        size_t o = (size_t)(b * C_ + oc) * T_ + t;
        g_x2[o] = acc[j] + ob[oc] + x[o];
    }
}

// ---------------- K10: h1 = relu(bn1(fc1 @ bn(x2))) ----------------
__global__ void __launch_bounds__(256) fc1_kernel(const float* __restrict__ n2g,
                                                  const float* __restrict__ n2b,
                                                  const float* __restrict__ w,
                                                  const float* __restrict__ bg,
                                                  const float* __restrict__ bb) {
    int blk = blockIdx.x;                 // 512
    int b = blk >> 5;
    int tt0 = (blk & 31) << 6;
    __shared__ float s_in[64][64];
    __shared__ float s_w[64 * 128];
    for (int i = threadIdx.x; i < 4096; i += 256) {
        int ci = i >> 6, tl = i & 63;
        s_in[ci][tl] = g_x2[(size_t)(b * C_ + ci) * T_ + tt0 + tl] * bnsc(n2g[ci]) + n2b[ci];
    }
    for (int i = threadIdx.x; i < 8192; i += 256) {
        int oc = i & 127, ci = i >> 7;
        s_w[ci * 128 + oc] = w[oc * 64 + ci];
    }
    __syncthreads();
    int tl = threadIdx.x & 63;
    int og = threadIdx.x >> 6;            // 4 groups x 32 oc
    float acc[32];
#pragma unroll
    for (int j = 0; j < 32; j++) acc[j] = 0.f;
    for (int ci = 0; ci < 64; ci++) {
        float xv = s_in[ci][tl];
        const float4* wp = (const float4*)&s_w[ci * 128 + og * 32];
#pragma unroll
        for (int q = 0; q < 8; q++) {
            float4 wv = wp[q];
            acc[q * 4 + 0] += xv * wv.x; acc[q * 4 + 1] += xv * wv.y;
            acc[q * 4 + 2] += xv * wv.z; acc[q * 4 + 3] += xv * wv.w;
        }
    }
    int t = tt0 + tl;
#pragma unroll
    for (int j = 0; j < 32; j++) {
        int oc = og * 32 + j;
        float r = acc[j] * bnsc(bg[oc]) + bb[oc];
        g_h1[(size_t)(b * C2_ + oc) * T_ + t] = fmaxf(r, 0.f);
    }
}

// ---------------- K11: paired FFT -> diag mix + relu -> paired IFFT ----------------
__device__ __forceinline__ float2 cmulf(float2 a, float2 b) {
    return make_float2(a.x * b.x - a.y * b.y, a.x * b.y + a.y * b.x);
}

__global__ void __launch_bounds__(256) fft_kernel(const float* __restrict__ fr,
                                                  const float* __restrict__ fi,
                                                  const float* __restrict__ frb,
                                                  const float* __restrict__ fib) {
    int blk = blockIdx.x;                 // B*64 = 1024
    int b = blk >> 6, j = blk & 63;
    int c0 = 2 * j, c1 = 2 * j + 1;
    __shared__ float2 sa[2048];
    __shared__ float2 sb[2048];
    const float* in0 = g_h1 + (size_t)(b * C2_ + c0) * T_;
    const float* in1 = g_h1 + (size_t)(b * C2_ + c1) * T_;
    for (int t = threadIdx.x; t < 2048; t += 256) {
        int p = __brev((unsigned)t) >> 21;
        sa[p] = make_float2(in0[t], in1[t]);
    }
    __syncthreads();
    // forward DIT (unnormalized, e^{-})
    int s = 0;
    for (int L = 1; L < 2048; L <<= 1, s++) {
        for (int jj = threadIdx.x; jj < 1024; jj += 256) {
            int pos = jj & (L - 1);
            int k0 = ((jj >> s) << (s + 1)) + pos;
            float2 wv = g_tw[pos << (10 - s)];
            float2 u = sa[k0];
            float2 t2 = cmulf(wv, sa[k0 + L]);
            sa[k0]     = make_float2(u.x + t2.x, u.y + t2.y);
            sa[k0 + L] = make_float2(u.x - t2.x, u.y - t2.y);
        }
        __syncthreads();
    }
    // spectral split + diag mix + relu + Hermitian recombine, bit-reversed into sb
    float fr0 = fr[c0 * 128 + c0], fi0 = fi[c0 * 128 + c0];
    float rb0 = frb[c0], ib0 = fib[c0];
    float fr1 = fr[c1 * 128 + c1], fi1 = fi[c1 * 128 + c1];
    float rb1 = frb[c1], ib1 = fib[c1];
    const float sc = 0.022097086912079612f;   // 1/sqrt(2048)
    for (int k = threadIdx.x; k < 2048; k += 256) {
        int m = (2048 - k) & 2047;
        float2 Zk = sa[k], Zm = sa[m];
        float Ar = 0.5f * sc * (Zk.x + Zm.x);
        float Ai = 0.5f * sc * (Zk.y - Zm.y);
        float Br = 0.5f * sc * (Zk.y + Zm.y);
        float Bi = 0.5f * sc * (Zm.x - Zk.x);
        // channel c0: Y(k) and Y(N-k) from A(N-k)=conj(A(k))
        float yk_r = fmaxf(Ar * fr0 - Ai * fi0 + rb0, 0.f);
        float yk_i = fmaxf(Ai * fr0 + Ar * fi0 + ib0, 0.f);
        float ym_r = fmaxf(Ar * fr0 + Ai * fi0 + rb0, 0.f);
        float ym_i = fmaxf(-Ai * fr0 + Ar * fi0 + ib0, 0.f);
        float Har = 0.5f * (yk_r + ym_r);
        float Hai = 0.5f * (yk_i - ym_i);
        // channel c1
        float zk_r = fmaxf(Br * fr1 - Bi * fi1 + rb1, 0.f);
        float zk_i = fmaxf(Bi * fr1 + Br * fi1 + ib1, 0.f);
        float zm_r = fmaxf(Br * fr1 + Bi * fi1 + rb1, 0.f);
        float zm_i = fmaxf(-Bi * fr1 + Br * fi1 + ib1, 0.f);
        float Hbr = 0.5f * (zk_r + zm_r);
        float Hbi = 0.5f * (zk_i - zm_i);
        sb[__brev((unsigned)k) >> 21] = make_float2(Har - Hbi, Hai + Hbr);
    }
    __syncthreads();
    // inverse DIT (conjugate twiddles, unnormalized)
    s = 0;
    for (int L = 1; L < 2048; L <<= 1, s++) {
        for (int jj = threadIdx.x; jj < 1024; jj += 256) {
            int pos = jj & (L - 1);
            int k0 = ((jj >> s) << (s + 1)) + pos;
            float2 wv = g_tw[pos << (10 - s)];
            wv.y = -wv.y;
            float2 u = sb[k0];
            float2 t2 = cmulf(wv, sb[k0 + L]);
            sb[k0]     = make_float2(u.x + t2.x, u.y + t2.y);
            sb[k0 + L] = make_float2(u.x - t2.x, u.y - t2.y);
        }
        __syncthreads();
    }
    float* out0 = g_h2 + (size_t)(b * C2_ + c0) * T_;
    float* out1 = g_h2 + (size_t)(b * C2_ + c1) * T_;
    for (int t = threadIdx.x; t < 2048; t += 256) {
        float2 wv = sb[t];
        out0[t] = wv.x * sc;
        out1[t] = wv.y * sc;
    }
}

// ---------------- K12: out = x2 + bn2(fc2 @ h2) ----------------
__global__ void __launch_bounds__(256) fc2_kernel(const float* __restrict__ w,
                                                  const float* __restrict__ bg,
                                                  const float* __restrict__ bb,
                                                  float* __restrict__ out) {
    int blk = blockIdx.x;                 // B*64 = 1024, t-tile 32
    int b = blk >> 6;
    int tt0 = (blk & 63) << 5;
    __shared__ float s_in[128][32];
    __shared__ float s_w[128 * 64];
    for (int i = threadIdx.x; i < 4096; i += 256) {
        int ci = i >> 5, tl = i & 31;
        s_in[ci][tl] = g_h2[(size_t)(b * C2_ + ci) * T_ + tt0 + tl];
    }
    for (int i = threadIdx.x; i < 8192; i += 256) {
        int oc = i & 63, ci = i >> 6;
        s_w[ci * 64 + oc] = w[oc * 128 + ci];
    }
    __syncthreads();
    int tl = threadIdx.x & 31;
    int og = threadIdx.x >> 5;            // 8 groups x 8 oc
    float acc[8];
#pragma unroll
    for (int j = 0; j < 8; j++) acc[j] = 0.f;
    for (int ci = 0; ci < 128; ci++) {
        float xv = s_in[ci][tl];
        const float4* wp = (const float4*)&s_w[ci * 64 + og * 8];
        float4 w0 = wp[0], w1 = wp[1];
        acc[0] += xv * w0.x; acc[1] += xv * w0.y;
        acc[2] += xv * w0.z; acc[3] += xv * w0.w;
        acc[4] += xv * w1.x; acc[5] += xv * w1.y;
        acc[6] += xv * w1.z; acc[7] += xv * w1.w;
    }
    int t = tt0 + tl;
#pragma unroll
    for (int j = 0; j < 8; j++) {
        int oc = og * 8 + j;
        size_t o = (size_t)(b * C_ + oc) * T_ + t;
        out[o] = acc[j] * bnsc(bg[oc]) + bb[oc] + g_x2[o];
    }
}

// ---------------- launch ----------------
extern "C" void kernel_launch(void* const* d_in, const int* in_sizes, int n_in,
                              void* d_out, int out_size) {
    const float* x      = (const float*)d_in[0];
    const float* n1_g   = (const float*)d_in[1];
    const float* n1_b   = (const float*)d_in[2];
    const float* wq     = (const float*)d_in[3];
    const float* bnq_g  = (const float*)d_in[4];
    const float* bnq_b  = (const float*)d_in[5];
    const float* wk     = (const float*)d_in[6];
    const float* bnk_g  = (const float*)d_in[7];
    const float* bnk_b  = (const float*)d_in[8];
    const float* wv     = (const float*)d_in[9];
    const float* lepe_w = (const float*)d_in[10];
    const float* lepe_b = (const float*)d_in[11];
    const float* out_w  = (const float*)d_in[12];
    const float* out_b  = (const float*)d_in[13];
    const float* n2_g   = (const float*)d_in[14];
    const float* n2_b   = (const float*)d_in[15];
    const float* fc1_w  = (const float*)d_in[16];
    const float* bn1_g  = (const float*)d_in[17];
    const float* bn1_b  = (const float*)d_in[18];
    const float* fr     = (const float*)d_in[19];
    const float* fi     = (const float*)d_in[20];
    const float* frb    = (const float*)d_in[21];
    const float* fib    = (const float*)d_in[22];
    const float* fc2_w  = (const float*)d_in[23];
    const float* bn2_g  = (const float*)d_in[24];
    const float* bn2_b  = (const float*)d_in[25];
    float* out = (float*)d_out;

    twiddle_kernel<<<4, 256>>>();
    bn_in_kernel<<<(B_*C_*T_)/256, 256>>>(x, n1_g, n1_b);
    conv3qk_kernel<<<1024, 128>>>(wq, bnq_g, bnq_b, wk, bnk_g, bnk_b);
    conv1v_kernel<<<512, 256>>>(wv);
    reduce_rs_kernel<<<(B_*C_*NR_)/256, 256>>>();
    gemm_ar_kernel<<<2048, 256>>>();
    topk_kernel<<<B_*NR_, 256>>>();
    transpose_kv_kernel<<<(B_*H_*NR_*32)/256, 256>>>();
    attn_kernel<<<(B_*H_*NR_)/4, 128>>>();
    fuse_o_kernel<<<512, 256>>>(x, lepe_w, lepe_b, out_w, out_b);
    fc1_kernel<<<512, 256>>>(n2_g, n2_b, fc1_w, bn1_g, bn1_b);
    fft_kernel<<<B_*64, 256>>>(fr, fi, frb, fib);
    fc2_kernel<<<1024, 256>>>(fc2_w, bn2_g, bn2_b, out);
    (void)in_sizes; (void)n_in; (void)out_size;
}